// round 4
// baseline (speedup 1.0000x reference)
#include <cuda_runtime.h>
#include <math.h>

#define NBODY 512
#define NVERT 6890
#define NJ 24
#define NCOL (NVERT*3)
#define KP 224               /* 207 pose + 10 beta + 1 template + 6 zero pad */
#define NTILE 216            /* ceil(6890/32) */
#define NCOLPAD (NTILE*96)   /* 20736 */
#define BN 64
#define BV 32

typedef unsigned long long ull;

// Scratch (device globals — no allocation in kernel_launch)
// PextP layout: [k][tile*96 + c*32 + vl], v = tile*32+vl
__device__ float d_PextP[(size_t)KP * NCOLPAD]; // ~18.6 MB
__device__ float d_LextT[KP * NBODY];           // [k][body]
__device__ float2 d_Gm2[(NBODY/2) * NJ * 12];   // body-pair interleaved
__device__ float d_JS[NJ * 3 * 10];
__device__ float d_Jt[NJ * 3];

__constant__ int c_par[NJ] = {0,0,0,0,1,2,3,4,5,6,7,8,9,9,9,12,13,14,16,17,18,19,20,21};

// ---- packed f32x2 helpers -------------------------------------------------
__device__ __forceinline__ ull ffma2(ull a, ull b, ull c) {
    ull d;
    asm("fma.rn.f32x2 %0, %1, %2, %3;" : "=l"(d) : "l"(a), "l"(b), "l"(c));
    return d;
}
__device__ __forceinline__ ull dup2(float x) {
    ull d; unsigned u = __float_as_uint(x);
    asm("mov.b64 %0, {%1, %1};" : "=l"(d) : "r"(u));
    return d;
}
__device__ __forceinline__ float2 unpack2(ull p) {
    float2 r;
    asm("mov.b64 {%0, %1}, %2;" : "=f"(r.x), "=f"(r.y) : "l"(p));
    return r;
}

// ---------------------------------------------------------------------------
// Build PextP: transpose + plane-tile pack.
// Block: one (v-tile, k-tile) pair; reads coalesced along k, writes along col.
// ---------------------------------------------------------------------------
__global__ void build_pextP_kernel(const float* __restrict__ posedirs,
                                   const float* __restrict__ shapedirs,
                                   const float* __restrict__ v_template)
{
    __shared__ float tile[96][33];
    int tileIdx = blockIdx.x;
    int kbase = blockIdx.y * 32;
    int tx = threadIdx.x, ty = threadIdx.y;  // 32 x 8
    int row0 = tileIdx * 96;                 // source row base (v*3+c space)
    for (int i = ty; i < 96; i += 8) {
        int row = row0 + i;
        int k = kbase + tx;
        float v = 0.f;
        if (row < NCOL) {
            if (k < 207)       v = posedirs[row * 207 + k];
            else if (k < 217)  v = shapedirs[row * 10 + (k - 207)];
            else if (k == 217) v = v_template[row];
        }
        tile[i][tx] = v;
    }
    __syncthreads();
    for (int kk = ty; kk < 32; kk += 8) {
        int k = kbase + kk;
#pragma unroll
        for (int c = 0; c < 3; c++) {
            // out col = c*32 + vl, source row = vl*3 + c
            d_PextP[(size_t)k * NCOLPAD + tileIdx * 96 + c * 32 + tx] = tile[tx * 3 + c][kk];
        }
    }
}

// ---------------------------------------------------------------------------
// Fold J_regressor into shape space once
// ---------------------------------------------------------------------------
__global__ void calc_js_kernel(const float* __restrict__ Jreg,
                               const float* __restrict__ shapedirs,
                               const float* __restrict__ v_template)
{
    int j = blockIdx.x;
    float acc[33];
#pragma unroll
    for (int q = 0; q < 33; q++) acc[q] = 0.f;
    for (int v = threadIdx.x; v < NVERT; v += 512) {
        float jr = Jreg[j * NVERT + v];
#pragma unroll
        for (int c = 0; c < 3; c++) {
            acc[c * 11] += jr * v_template[v * 3 + c];
#pragma unroll
            for (int b = 0; b < 10; b++)
                acc[c * 11 + 1 + b] += jr * shapedirs[(v * 3 + c) * 10 + b];
        }
    }
    __shared__ float red[16][33];
    int lane = threadIdx.x & 31, wid = threadIdx.x >> 5;
#pragma unroll
    for (int q = 0; q < 33; q++) {
        float s = acc[q];
        for (int o = 16; o; o >>= 1) s += __shfl_down_sync(0xffffffffu, s, o);
        if (lane == 0) red[wid][q] = s;
    }
    __syncthreads();
    if (threadIdx.x < 33) {
        int q = threadIdx.x;
        float s = 0.f;
        for (int w = 0; w < 16; w++) s += red[w][q];
        int c = q / 11, r = q - c * 11;
        if (r == 0) d_Jt[j * 3 + c] = s;
        else        d_JS[(j * 3 + c) * 10 + (r - 1)] = s;
    }
}

// ---------------------------------------------------------------------------
// Per-body prep: Rodrigues, LextT, joints, chain, G'. One warp per body.
// ---------------------------------------------------------------------------
__global__ void body_kernel(const float* __restrict__ beta,
                            const float* __restrict__ pose)
{
    int n = blockIdx.x;
    int lane = threadIdx.x;
    __shared__ float sR[NJ][9];
    __shared__ float sJ[NJ][3];
    __shared__ float sG[NJ][12];
    __shared__ float sBeta[10];

    if (lane < 10) sBeta[lane] = beta[n * 10 + lane];
    if (lane < NJ) {
        float x = pose[n * 72 + lane * 3 + 0];
        float y = pose[n * 72 + lane * 3 + 1];
        float z = pose[n * 72 + lane * 3 + 2];
        float th = sqrtf(x * x + y * y + z * z) + 1e-8f;
        float inv = 1.0f / th;
        x *= inv; y *= inv; z *= inv;
        float s, c;
        sincosf(th, &s, &c);
        float C = 1.0f - c;
        sR[lane][0] = c + C * x * x;     sR[lane][1] = C * x * y - s * z; sR[lane][2] = C * x * z + s * y;
        sR[lane][3] = C * x * y + s * z; sR[lane][4] = c + C * y * y;     sR[lane][5] = C * y * z - s * x;
        sR[lane][6] = C * x * z - s * y; sR[lane][7] = C * y * z + s * x; sR[lane][8] = c + C * z * z;
    }
    __syncwarp();

    for (int t = lane; t < 207; t += 32) {
        int jj = 1 + t / 9, e = t - (t / 9) * 9;
        d_LextT[t * NBODY + n] = sR[jj][e] - ((e == 0 || e == 4 || e == 8) ? 1.0f : 0.0f);
    }
    for (int t = lane; t < 17; t += 32) {
        int k = 207 + t;
        d_LextT[k * NBODY + n] = (t < 10) ? sBeta[t] : ((k == 217) ? 1.0f : 0.0f);
    }

    for (int t = lane; t < 72; t += 32) {
        int jj = t / 3, c = t - jj * 3;
        float s = d_Jt[jj * 3 + c];
#pragma unroll
        for (int b = 0; b < 10; b++) s += d_JS[(jj * 3 + c) * 10 + b] * sBeta[b];
        sJ[jj][c] = s;
    }
    __syncwarp();

    if (lane < 12) {
        int r = lane >> 2, cc = lane & 3;
        sG[0][lane] = (cc < 3) ? sR[0][r * 3 + cc] : sJ[0][r];
    }
    __syncwarp();
    for (int i = 1; i < NJ; i++) {
        int p = c_par[i];
        float val = 0.f;
        if (lane < 12) {
            int r = lane >> 2, cc = lane & 3;
            float t0, t1, t2;
            if (cc < 3) { t0 = sR[i][cc]; t1 = sR[i][3 + cc]; t2 = sR[i][6 + cc]; }
            else { t0 = sJ[i][0] - sJ[p][0]; t1 = sJ[i][1] - sJ[p][1]; t2 = sJ[i][2] - sJ[p][2]; }
            val = sG[p][r * 4 + 0] * t0 + sG[p][r * 4 + 1] * t1 + sG[p][r * 4 + 2] * t2;
            if (cc == 3) val += sG[p][r * 4 + 3];
        }
        __syncwarp();
        if (lane < 12) sG[i][lane] = val;
        __syncwarp();
    }

    for (int t = lane; t < 72; t += 32) {
        int jj = t / 3, r = t - jj * 3;
        float rj = sG[jj][r * 4 + 0] * sJ[jj][0] + sG[jj][r * 4 + 1] * sJ[jj][1]
                 + sG[jj][r * 4 + 2] * sJ[jj][2];
        sG[jj][r * 4 + 3] -= rj;
    }
    __syncwarp();
    // pair-interleaved global store
    for (int t = lane; t < NJ * 12; t += 32) {
        float g = sG[t / 12][t - (t / 12) * 12];
        if (n & 1) d_Gm2[(n >> 1) * (NJ * 12) + t].y = g;
        else       d_Gm2[(n >> 1) * (NJ * 12) + t].x = g;
    }
}

// ---------------------------------------------------------------------------
// Main fused kernel. Block: 128 thr = 16 tx x 8 ty. Tile 64 bodies x 32 verts.
// Thread: 4 body-pairs x (2 verts x 3 coords). B pre-duplicated in smem.
// ---------------------------------------------------------------------------
__global__ void __launch_bounds__(128, 4)
smpl_main_kernel(const float* __restrict__ weights, float* __restrict__ out)
{
    __shared__ __align__(16) float As[32][64];    // [k][body]
    __shared__ __align__(16) float Bd[32][194];   // [k][col*2] duplicated pairs
    __shared__ float Ws[32][25];                  // [vl][joint]
    __shared__ __align__(16) float2 Gs2[32 * 72]; // [pair][6 joints * 12]

    int tid = threadIdx.x;
    int tx = tid & 15, ty = tid >> 4;
    int nBase = blockIdx.y * BN;
    int vBase = blockIdx.x * BV;
    int tileBase = blockIdx.x * 96;

    ull vp2[4][6];   // [pair][vv*3+c]
#pragma unroll
    for (int p = 0; p < 4; p++)
#pragma unroll
        for (int j = 0; j < 6; j++) vp2[p][j] = 0ull;

    // ---- Phase 1: v_posed GEMM (K=224), f32x2 packed over body pairs ----
    for (int k0 = 0; k0 < KP; k0 += 32) {
#pragma unroll
        for (int t = 0; t < 4; t++) {
            int idx = tid + t * 128;
            int kk = idx >> 4, c4 = idx & 15;
            *(float4*)&As[kk][c4 * 4] =
                *(const float4*)&d_LextT[(k0 + kk) * NBODY + nBase + c4 * 4];
        }
#pragma unroll
        for (int t = 0; t < 6; t++) {
            int idx = tid + t * 128;
            int kk = idx / 24, c4 = idx - kk * 24;
            float4 v = *(const float4*)&d_PextP[(size_t)(k0 + kk) * NCOLPAD + tileBase + c4 * 4];
            float2* dst = (float2*)&Bd[kk][c4 * 8];
            dst[0] = make_float2(v.x, v.x);
            dst[1] = make_float2(v.y, v.y);
            dst[2] = make_float2(v.z, v.z);
            dst[3] = make_float2(v.w, v.w);
        }
        __syncthreads();
#pragma unroll
        for (int kk = 0; kk < 32; kk++) {
            ulonglong2 A0 = *(const ulonglong2*)&As[kk][ty * 8];
            ulonglong2 A1 = *(const ulonglong2*)&As[kk][ty * 8 + 4];
            ull b[6];
#pragma unroll
            for (int vv = 0; vv < 2; vv++)
#pragma unroll
                for (int c = 0; c < 3; c++)
                    b[vv * 3 + c] = *(const ull*)&Bd[kk][(c * 32 + tx + vv * 16) * 2];
#pragma unroll
            for (int j = 0; j < 6; j++) {
                vp2[0][j] = ffma2(A0.x, b[j], vp2[0][j]);
                vp2[1][j] = ffma2(A0.y, b[j], vp2[1][j]);
                vp2[2][j] = ffma2(A1.x, b[j], vp2[2][j]);
                vp2[3][j] = ffma2(A1.y, b[j], vp2[3][j]);
            }
        }
        __syncthreads();
    }

    // ---- Phase 2: LBS ----
    for (int t = tid; t < BV * 24; t += 128) {
        int vl = t / 24, j2 = t - vl * 24;
        int v = vBase + vl;
        Ws[vl][j2] = (v < NVERT) ? weights[v * 24 + j2] : 0.f;
    }

    ull o2[4][6];
#pragma unroll
    for (int p = 0; p < 4; p++)
#pragma unroll
        for (int j = 0; j < 6; j++) o2[p][j] = 0ull;

    int pBase = nBase >> 1;
    for (int jc = 0; jc < 4; jc++) {
        __syncthreads();
        for (int t = tid; t < 32 * 72; t += 128) {
            int pl = t / 72, e = t - pl * 72;
            Gs2[t] = d_Gm2[(pBase + pl) * (NJ * 12) + jc * 72 + e];
        }
        __syncthreads();
#pragma unroll
        for (int jj = 0; jj < 6; jj++) {
            ull w0 = dup2(Ws[tx][jc * 6 + jj]);
            ull w1 = dup2(Ws[tx + 16][jc * 6 + jj]);
#pragma unroll
            for (int q = 0; q < 4; q++) {
                const ull* g = (const ull*)&Gs2[(ty * 4 + q) * 72 + jj * 12];
#pragma unroll
                for (int c = 0; c < 3; c++) {
                    ull g0 = g[c * 4 + 0], g1 = g[c * 4 + 1];
                    ull g2 = g[c * 4 + 2], g3 = g[c * 4 + 3];
                    ull t0 = ffma2(g0, vp2[q][0], ffma2(g1, vp2[q][1], ffma2(g2, vp2[q][2], g3)));
                    o2[q][c] = ffma2(w0, t0, o2[q][c]);
                    ull t1 = ffma2(g0, vp2[q][3], ffma2(g1, vp2[q][4], ffma2(g2, vp2[q][5], g3)));
                    o2[q][3 + c] = ffma2(w1, t1, o2[q][3 + c]);
                }
            }
        }
    }

    // ---- Store ----
#pragma unroll
    for (int q = 0; q < 4; q++) {
        int n0 = nBase + ty * 8 + 2 * q;
#pragma unroll
        for (int vv = 0; vv < 2; vv++) {
            int v = vBase + tx + vv * 16;
            if (v < NVERT) {
                size_t b0 = ((size_t)n0 * NVERT + v) * 3;
                size_t b1 = ((size_t)(n0 + 1) * NVERT + v) * 3;
#pragma unroll
                for (int c = 0; c < 3; c++) {
                    float2 pr = unpack2(o2[q][vv * 3 + c]);
                    out[b0 + c] = pr.x;
                    out[b1 + c] = pr.y;
                }
            }
        }
    }
}

// ---------------------------------------------------------------------------
extern "C" void kernel_launch(void* const* d_in, const int* in_sizes, int n_in,
                              void* d_out, int out_size)
{
    const float* beta        = (const float*)d_in[0];
    const float* pose        = (const float*)d_in[1];
    const float* v_template  = (const float*)d_in[2];
    const float* shapedirs   = (const float*)d_in[3];
    const float* posedirs    = (const float*)d_in[4];
    const float* J_regressor = (const float*)d_in[5];
    const float* weights     = (const float*)d_in[6];
    float* out = (float*)d_out;

    build_pextP_kernel<<<dim3(NTILE, KP / 32), dim3(32, 8)>>>(posedirs, shapedirs, v_template);
    calc_js_kernel<<<NJ, 512>>>(J_regressor, shapedirs, v_template);
    body_kernel<<<NBODY, 32>>>(beta, pose);
    smpl_main_kernel<<<dim3(NTILE, NBODY / BN), 128>>>(weights, out);
}

// round 5
// speedup vs baseline: 1.1848x; 1.1848x over previous
#include <cuda_runtime.h>
#include <math.h>

#define NBODY 512
#define NVERT 6890
#define NJ 24
#define NCOL (NVERT*3)
#define KP 224               /* 207 pose + 10 beta + 1 template + 6 zero pad */
#define NTILE 216
#define NCOLPAD (NTILE*96)   /* 20736, col = v*3+c */
#define BN 64
#define BV 32

typedef unsigned long long ull;

// Scratch (device globals — no allocation in kernel_launch)
__device__ float d_PextT[(size_t)KP * NCOLPAD]; // [k][col], col = v*3+c
__device__ float d_LextT[KP * NBODY];           // [k][body]
__device__ float2 d_Gm2[(NBODY/2) * NJ * 12];   // body-pair interleaved
__device__ float d_JS[NJ * 3 * 10];
__device__ float d_Jt[NJ * 3];

__constant__ int c_par[NJ] = {0,0,0,0,1,2,3,4,5,6,7,8,9,9,9,12,13,14,16,17,18,19,20,21};

// ---- packed f32x2 helpers -------------------------------------------------
__device__ __forceinline__ ull ffma2(ull a, ull b, ull c) {
    ull d;
    asm("fma.rn.f32x2 %0, %1, %2, %3;" : "=l"(d) : "l"(a), "l"(b), "l"(c));
    return d;
}
__device__ __forceinline__ ull dup2(float x) {
    ull d; unsigned u = __float_as_uint(x);
    asm("mov.b64 %0, {%1, %1};" : "=l"(d) : "r"(u));
    return d;
}
__device__ __forceinline__ float2 unpack2(ull p) {
    float2 r;
    asm("mov.b64 {%0, %1}, %2;" : "=f"(r.x), "=f"(r.y) : "l"(p));
    return r;
}
// ---- cp.async helpers ------------------------------------------------------
__device__ __forceinline__ void cp_async16(unsigned s, const void* g) {
    asm volatile("cp.async.cg.shared.global [%0], [%1], 16;\n" :: "r"(s), "l"(g));
}
__device__ __forceinline__ void cp_commit() {
    asm volatile("cp.async.commit_group;\n");
}
template<int N> __device__ __forceinline__ void cp_wait() {
    asm volatile("cp.async.wait_group %0;\n" :: "n"(N));
}

// ---------------------------------------------------------------------------
// Build PextT[k][col] (transpose-pack), col = v*3+c, padded cols zero.
// ---------------------------------------------------------------------------
__global__ void build_pextT_kernel(const float* __restrict__ posedirs,
                                   const float* __restrict__ shapedirs,
                                   const float* __restrict__ v_template)
{
    __shared__ float tile[32][33];
    int rbase = blockIdx.x * 32;
    int kbase = blockIdx.y * 32;
    int tx = threadIdx.x, ty = threadIdx.y;   // 32 x 8
#pragma unroll
    for (int i = 0; i < 4; i++) {
        int row = rbase + ty * 4 + i;
        int k = kbase + tx;
        float v = 0.f;
        if (row < NCOL) {
            if (k < 207)       v = posedirs[row * 207 + k];
            else if (k < 217)  v = shapedirs[row * 10 + (k - 207)];
            else if (k == 217) v = v_template[row];
        }
        tile[ty * 4 + i][tx] = v;
    }
    __syncthreads();
#pragma unroll
    for (int i = 0; i < 4; i++) {
        int k = kbase + ty * 4 + i;
        int row = rbase + tx;
        d_PextT[(size_t)k * NCOLPAD + row] = tile[tx][ty * 4 + i];
    }
}

// ---------------------------------------------------------------------------
// Fold J_regressor into shape space once
// ---------------------------------------------------------------------------
__global__ void calc_js_kernel(const float* __restrict__ Jreg,
                               const float* __restrict__ shapedirs,
                               const float* __restrict__ v_template)
{
    int j = blockIdx.x;
    float acc[33];
#pragma unroll
    for (int q = 0; q < 33; q++) acc[q] = 0.f;
    for (int v = threadIdx.x; v < NVERT; v += 512) {
        float jr = Jreg[j * NVERT + v];
#pragma unroll
        for (int c = 0; c < 3; c++) {
            acc[c * 11] += jr * v_template[v * 3 + c];
#pragma unroll
            for (int b = 0; b < 10; b++)
                acc[c * 11 + 1 + b] += jr * shapedirs[(v * 3 + c) * 10 + b];
        }
    }
    __shared__ float red[16][33];
    int lane = threadIdx.x & 31, wid = threadIdx.x >> 5;
#pragma unroll
    for (int q = 0; q < 33; q++) {
        float s = acc[q];
        for (int o = 16; o; o >>= 1) s += __shfl_down_sync(0xffffffffu, s, o);
        if (lane == 0) red[wid][q] = s;
    }
    __syncthreads();
    if (threadIdx.x < 33) {
        int q = threadIdx.x;
        float s = 0.f;
        for (int w = 0; w < 16; w++) s += red[w][q];
        int c = q / 11, r = q - c * 11;
        if (r == 0) d_Jt[j * 3 + c] = s;
        else        d_JS[(j * 3 + c) * 10 + (r - 1)] = s;
    }
}

// ---------------------------------------------------------------------------
// Per-body prep: Rodrigues, LextT, joints, chain, G'. One warp per body.
// ---------------------------------------------------------------------------
__global__ void body_kernel(const float* __restrict__ beta,
                            const float* __restrict__ pose)
{
    int n = blockIdx.x;
    int lane = threadIdx.x;
    __shared__ float sR[NJ][9];
    __shared__ float sJ[NJ][3];
    __shared__ float sG[NJ][12];
    __shared__ float sBeta[10];

    if (lane < 10) sBeta[lane] = beta[n * 10 + lane];
    if (lane < NJ) {
        float x = pose[n * 72 + lane * 3 + 0];
        float y = pose[n * 72 + lane * 3 + 1];
        float z = pose[n * 72 + lane * 3 + 2];
        float th = sqrtf(x * x + y * y + z * z) + 1e-8f;
        float inv = 1.0f / th;
        x *= inv; y *= inv; z *= inv;
        float s, c;
        sincosf(th, &s, &c);
        float C = 1.0f - c;
        sR[lane][0] = c + C * x * x;     sR[lane][1] = C * x * y - s * z; sR[lane][2] = C * x * z + s * y;
        sR[lane][3] = C * x * y + s * z; sR[lane][4] = c + C * y * y;     sR[lane][5] = C * y * z - s * x;
        sR[lane][6] = C * x * z - s * y; sR[lane][7] = C * y * z + s * x; sR[lane][8] = c + C * z * z;
    }
    __syncwarp();

    for (int t = lane; t < 207; t += 32) {
        int jj = 1 + t / 9, e = t - (t / 9) * 9;
        d_LextT[t * NBODY + n] = sR[jj][e] - ((e == 0 || e == 4 || e == 8) ? 1.0f : 0.0f);
    }
    for (int t = lane; t < 17; t += 32) {
        int k = 207 + t;
        d_LextT[k * NBODY + n] = (t < 10) ? sBeta[t] : ((k == 217) ? 1.0f : 0.0f);
    }

    for (int t = lane; t < 72; t += 32) {
        int jj = t / 3, c = t - jj * 3;
        float s = d_Jt[jj * 3 + c];
#pragma unroll
        for (int b = 0; b < 10; b++) s += d_JS[(jj * 3 + c) * 10 + b] * sBeta[b];
        sJ[jj][c] = s;
    }
    __syncwarp();

    if (lane < 12) {
        int r = lane >> 2, cc = lane & 3;
        sG[0][lane] = (cc < 3) ? sR[0][r * 3 + cc] : sJ[0][r];
    }
    __syncwarp();
    for (int i = 1; i < NJ; i++) {
        int p = c_par[i];
        float val = 0.f;
        if (lane < 12) {
            int r = lane >> 2, cc = lane & 3;
            float t0, t1, t2;
            if (cc < 3) { t0 = sR[i][cc]; t1 = sR[i][3 + cc]; t2 = sR[i][6 + cc]; }
            else { t0 = sJ[i][0] - sJ[p][0]; t1 = sJ[i][1] - sJ[p][1]; t2 = sJ[i][2] - sJ[p][2]; }
            val = sG[p][r * 4 + 0] * t0 + sG[p][r * 4 + 1] * t1 + sG[p][r * 4 + 2] * t2;
            if (cc == 3) val += sG[p][r * 4 + 3];
        }
        __syncwarp();
        if (lane < 12) sG[i][lane] = val;
        __syncwarp();
    }

    for (int t = lane; t < 72; t += 32) {
        int jj = t / 3, r = t - jj * 3;
        float rj = sG[jj][r * 4 + 0] * sJ[jj][0] + sG[jj][r * 4 + 1] * sJ[jj][1]
                 + sG[jj][r * 4 + 2] * sJ[jj][2];
        sG[jj][r * 4 + 3] -= rj;
    }
    __syncwarp();
    for (int t = lane; t < NJ * 12; t += 32) {
        float g = sG[t / 12][t - (t / 12) * 12];
        if (n & 1) d_Gm2[(n >> 1) * (NJ * 12) + t].y = g;
        else       d_Gm2[(n >> 1) * (NJ * 12) + t].x = g;
    }
}

// ---------------------------------------------------------------------------
// Main fused kernel. 128 thr = 16 tx x 8 ty. Tile 64 bodies x 32 verts.
// Phase 1: R2 inner loop + cp.async double buffering.
// Smem union: phase1 {As[2],Bs[2]} 42KB / phase2 {Gs2, Ws} 22KB.
// ---------------------------------------------------------------------------
#define AS_OFF(buf, kk, c) ((buf) * 2048 + (kk) * 64 + (c))
#define BS_OFF(buf, kk, c) (4096 + (buf) * 3200 + (kk) * 100 + (c))
#define GS_STRIDE 73  /* float2 units; 4*73*2 % 32 = 8 -> ty rows on distinct banks */

__global__ void __launch_bounds__(128, 4)
smpl_main_kernel(const float* __restrict__ weights, float* __restrict__ out)
{
    __shared__ __align__(16) float smemf[10496];   // 42 KB

    float* Ws = smemf + 32 * GS_STRIDE * 2;        // [32][25] after Gs2
    float2* Gs2 = (float2*)smemf;

    int tid = threadIdx.x;
    int tx = tid & 15, ty = tid >> 4;
    int nBase = blockIdx.y * BN;
    int vBase = blockIdx.x * BV;
    int colBase = blockIdx.x * 96;

    unsigned smem_base = (unsigned)__cvta_generic_to_shared(smemf);

    ull vp2[4][6];
#pragma unroll
    for (int p = 0; p < 4; p++)
#pragma unroll
        for (int j = 0; j < 6; j++) vp2[p][j] = 0ull;

    // ---- Phase 1 prologue: async-load tile 0 into buf 0 ----
    {
#pragma unroll
        for (int t = 0; t < 4; t++) {
            int idx = tid + t * 128;
            int kk = idx >> 4, c4 = idx & 15;
            cp_async16(smem_base + AS_OFF(0, kk, c4 * 4) * 4,
                       &d_LextT[kk * NBODY + nBase + c4 * 4]);
        }
#pragma unroll
        for (int t = 0; t < 6; t++) {
            int idx = tid + t * 128;
            int kk = idx / 24, c4 = idx - kk * 24;
            cp_async16(smem_base + BS_OFF(0, kk, c4 * 4) * 4,
                       &d_PextT[(size_t)kk * NCOLPAD + colBase + c4 * 4]);
        }
        cp_commit();
    }

    for (int tt = 0; tt < 7; tt++) {
        int cur = tt & 1;
        if (tt < 6) {
            int nb = cur ^ 1;
            int k1 = (tt + 1) * 32;
#pragma unroll
            for (int t = 0; t < 4; t++) {
                int idx = tid + t * 128;
                int kk = idx >> 4, c4 = idx & 15;
                cp_async16(smem_base + AS_OFF(nb, kk, c4 * 4) * 4,
                           &d_LextT[(k1 + kk) * NBODY + nBase + c4 * 4]);
            }
#pragma unroll
            for (int t = 0; t < 6; t++) {
                int idx = tid + t * 128;
                int kk = idx / 24, c4 = idx - kk * 24;
                cp_async16(smem_base + BS_OFF(nb, kk, c4 * 4) * 4,
                           &d_PextT[(size_t)(k1 + kk) * NCOLPAD + colBase + c4 * 4]);
            }
            cp_commit();
            cp_wait<1>();
        } else {
            cp_wait<0>();
        }
        __syncthreads();

#pragma unroll
        for (int kk = 0; kk < 32; kk++) {
            ulonglong2 A0 = *(const ulonglong2*)&smemf[AS_OFF(cur, kk, ty * 8)];
            ulonglong2 A1 = *(const ulonglong2*)&smemf[AS_OFF(cur, kk, ty * 8 + 4)];
            float2 b01 = *(const float2*)&smemf[BS_OFF(cur, kk, tx * 6)];
            float2 b23 = *(const float2*)&smemf[BS_OFF(cur, kk, tx * 6 + 2)];
            float2 b45 = *(const float2*)&smemf[BS_OFF(cur, kk, tx * 6 + 4)];
            ull bd[6];
            bd[0] = dup2(b01.x); bd[1] = dup2(b01.y);
            bd[2] = dup2(b23.x); bd[3] = dup2(b23.y);
            bd[4] = dup2(b45.x); bd[5] = dup2(b45.y);
#pragma unroll
            for (int j = 0; j < 6; j++) {
                vp2[0][j] = ffma2(A0.x, bd[j], vp2[0][j]);
                vp2[1][j] = ffma2(A0.y, bd[j], vp2[1][j]);
                vp2[2][j] = ffma2(A1.x, bd[j], vp2[2][j]);
                vp2[3][j] = ffma2(A1.y, bd[j], vp2[3][j]);
            }
        }
        __syncthreads();
    }

    // ---- Phase 2: LBS (smem reused: Gs2 + Ws) ----
    for (int t = tid; t < BV * 24; t += 128) {
        int vl = t / 24, j2 = t - vl * 24;
        int v = vBase + vl;
        Ws[vl * 25 + j2] = (v < NVERT) ? weights[v * 24 + j2] : 0.f;
    }

    ull o2[4][6];
#pragma unroll
    for (int p = 0; p < 4; p++)
#pragma unroll
        for (int j = 0; j < 6; j++) o2[p][j] = 0ull;

    int pBase = nBase >> 1;
    for (int jc = 0; jc < 4; jc++) {
        __syncthreads();
        for (int t = tid; t < 32 * 72; t += 128) {
            int pl = t / 72, e = t - pl * 72;
            Gs2[pl * GS_STRIDE + e] = d_Gm2[(pBase + pl) * (NJ * 12) + jc * 72 + e];
        }
        __syncthreads();
#pragma unroll
        for (int jj = 0; jj < 6; jj++) {
            ull w0 = dup2(Ws[(tx * 2) * 25 + jc * 6 + jj]);
            ull w1 = dup2(Ws[(tx * 2 + 1) * 25 + jc * 6 + jj]);
#pragma unroll
            for (int q = 0; q < 4; q++) {
                const ull* g = (const ull*)&Gs2[(ty * 4 + q) * GS_STRIDE + jj * 12];
#pragma unroll
                for (int c = 0; c < 3; c++) {
                    ull g0 = g[c * 4 + 0], g1 = g[c * 4 + 1];
                    ull g2 = g[c * 4 + 2], g3 = g[c * 4 + 3];
                    ull t0 = ffma2(g0, vp2[q][0], ffma2(g1, vp2[q][1], ffma2(g2, vp2[q][2], g3)));
                    o2[q][c] = ffma2(w0, t0, o2[q][c]);
                    ull t1 = ffma2(g0, vp2[q][3], ffma2(g1, vp2[q][4], ffma2(g2, vp2[q][5], g3)));
                    o2[q][3 + c] = ffma2(w1, t1, o2[q][3 + c]);
                }
            }
        }
    }

    // ---- Store ----
#pragma unroll
    for (int q = 0; q < 4; q++) {
        int n0 = nBase + ty * 8 + 2 * q;
#pragma unroll
        for (int vv = 0; vv < 2; vv++) {
            int v = vBase + tx * 2 + vv;
            if (v < NVERT) {
                size_t b0 = ((size_t)n0 * NVERT + v) * 3;
                size_t b1 = ((size_t)(n0 + 1) * NVERT + v) * 3;
#pragma unroll
                for (int c = 0; c < 3; c++) {
                    float2 pr = unpack2(o2[q][vv * 3 + c]);
                    out[b0 + c] = pr.x;
                    out[b1 + c] = pr.y;
                }
            }
        }
    }
}

// ---------------------------------------------------------------------------
extern "C" void kernel_launch(void* const* d_in, const int* in_sizes, int n_in,
                              void* d_out, int out_size)
{
    const float* beta        = (const float*)d_in[0];
    const float* pose        = (const float*)d_in[1];
    const float* v_template  = (const float*)d_in[2];
    const float* shapedirs   = (const float*)d_in[3];
    const float* posedirs    = (const float*)d_in[4];
    const float* J_regressor = (const float*)d_in[5];
    const float* weights     = (const float*)d_in[6];
    float* out = (float*)d_out;

    build_pextT_kernel<<<dim3(NCOLPAD / 32, KP / 32), dim3(32, 8)>>>(posedirs, shapedirs, v_template);
    calc_js_kernel<<<NJ, 512>>>(J_regressor, shapedirs, v_template);
    body_kernel<<<NBODY, 32>>>(beta, pose);
    smpl_main_kernel<<<dim3(NTILE, NBODY / BN), 128>>>(weights, out);
}

// round 7
// speedup vs baseline: 1.2617x; 1.0649x over previous
#include <cuda_runtime.h>
#include <math.h>

#define NBODY 512
#define NVERT 6890
#define NJ 24
#define NCOL (NVERT*3)
#define KP 224               /* 207 pose + 10 beta + 1 template + 6 zero pad */
#define NTILE 216
#define NCOLPAD (NTILE*96)   /* 20736, col = v*3+c */
#define BN 64
#define BV 32

typedef unsigned long long ull;

// Scratch (device globals — no allocation anywhere)
__device__ float d_PextT[(size_t)KP * NCOLPAD]; // [k][col], col = v*3+c
__device__ float d_LextT[KP * NBODY];           // [k][body]
__device__ float2 d_Gm2[(NBODY/2) * NJ * 12];   // body-pair interleaved
__device__ float d_JS[NJ * 3 * 10];
__device__ float d_Jt[NJ * 3];

__constant__ int c_par[NJ] = {0,0,0,0,1,2,3,4,5,6,7,8,9,9,9,12,13,14,16,17,18,19,20,21};

// ---- packed f32x2 helpers -------------------------------------------------
__device__ __forceinline__ ull ffma2(ull a, ull b, ull c) {
    ull d;
    asm("fma.rn.f32x2 %0, %1, %2, %3;" : "=l"(d) : "l"(a), "l"(b), "l"(c));
    return d;
}
__device__ __forceinline__ ull dup2(float x) {
    ull d; unsigned u = __float_as_uint(x);
    asm("mov.b64 %0, {%1, %1};" : "=l"(d) : "r"(u));
    return d;
}
__device__ __forceinline__ float2 unpack2(ull p) {
    float2 r;
    asm("mov.b64 {%0, %1}, %2;" : "=f"(r.x), "=f"(r.y) : "l"(p));
    return r;
}
// ---- cp.async helpers ------------------------------------------------------
__device__ __forceinline__ void cp_async16(unsigned s, const void* g) {
    asm volatile("cp.async.cg.shared.global [%0], [%1], 16;\n" :: "r"(s), "l"(g));
}
__device__ __forceinline__ void cp_commit() {
    asm volatile("cp.async.commit_group;\n");
}
template<int N> __device__ __forceinline__ void cp_wait() {
    asm volatile("cp.async.wait_group %0;\n" :: "n"(N));
}

// ---------------------------------------------------------------------------
// Fused prep: blocks [0,4536) build PextT transpose tiles;
// blocks [4536,4608) fold J_regressor into shape space (72 = joint*coord).
// blockDim = (32,8).
// ---------------------------------------------------------------------------
__global__ void prep_kernel(const float* __restrict__ posedirs,
                            const float* __restrict__ shapedirs,
                            const float* __restrict__ v_template,
                            const float* __restrict__ Jreg)
{
    int bid = blockIdx.x;
    int tx = threadIdx.x, ty = threadIdx.y;
    if (bid < 4536) {
        __shared__ float tile[32][33];
        int rbase = (bid % 648) * 32;
        int kbase = (bid / 648) * 32;
#pragma unroll
        for (int i = 0; i < 4; i++) {
            int row = rbase + ty * 4 + i;
            int k = kbase + tx;
            float v = 0.f;
            if (row < NCOL) {
                if (k < 207)       v = posedirs[row * 207 + k];
                else if (k < 217)  v = shapedirs[row * 10 + (k - 207)];
                else if (k == 217) v = v_template[row];
            }
            tile[ty * 4 + i][tx] = v;
        }
        __syncthreads();
#pragma unroll
        for (int i = 0; i < 4; i++) {
            int k = kbase + ty * 4 + i;
            int row = rbase + tx;
            d_PextT[(size_t)k * NCOLPAD + row] = tile[tx][ty * 4 + i];
        }
    } else {
        int jc = bid - 4536;
        int j = jc / 3, c = jc - j * 3;
        int tid = ty * 32 + tx;
        float acc[11];
#pragma unroll
        for (int q = 0; q < 11; q++) acc[q] = 0.f;
        for (int v = tid; v < NVERT; v += 256) {
            float jr = Jreg[j * NVERT + v];
            acc[0] += jr * v_template[v * 3 + c];
#pragma unroll
            for (int b = 0; b < 10; b++)
                acc[1 + b] += jr * shapedirs[(v * 3 + c) * 10 + b];
        }
        __shared__ float red[8][11];
        int lane = tid & 31, wid = tid >> 5;
#pragma unroll
        for (int q = 0; q < 11; q++) {
            float s = acc[q];
            for (int o = 16; o; o >>= 1) s += __shfl_down_sync(0xffffffffu, s, o);
            if (lane == 0) red[wid][q] = s;
        }
        __syncthreads();
        if (tid < 11) {
            int q = tid;
            float s = 0.f;
            for (int w = 0; w < 8; w++) s += red[w][q];
            if (q == 0) d_Jt[j * 3 + c] = s;
            else        d_JS[(j * 3 + c) * 10 + (q - 1)] = s;
        }
    }
}

// ---------------------------------------------------------------------------
// Per-body prep: Rodrigues, LextT, joints, chain, G'. 8 warps/block, 1 warp/body.
// ---------------------------------------------------------------------------
__global__ void __launch_bounds__(256)
body_kernel(const float* __restrict__ beta, const float* __restrict__ pose)
{
    int w = threadIdx.x >> 5;
    int lane = threadIdx.x & 31;
    int n = blockIdx.x * 8 + w;

    __shared__ float sR[8][NJ][9];
    __shared__ float sJ[8][NJ][3];
    __shared__ float sG[8][NJ][12];
    __shared__ float sBeta[8][10];

    if (lane < 10) sBeta[w][lane] = beta[n * 10 + lane];
    if (lane < NJ) {
        float x = pose[n * 72 + lane * 3 + 0];
        float y = pose[n * 72 + lane * 3 + 1];
        float z = pose[n * 72 + lane * 3 + 2];
        float th = sqrtf(x * x + y * y + z * z) + 1e-8f;
        float inv = 1.0f / th;
        x *= inv; y *= inv; z *= inv;
        float s, c;
        sincosf(th, &s, &c);
        float C = 1.0f - c;
        sR[w][lane][0] = c + C * x * x;     sR[w][lane][1] = C * x * y - s * z; sR[w][lane][2] = C * x * z + s * y;
        sR[w][lane][3] = C * x * y + s * z; sR[w][lane][4] = c + C * y * y;     sR[w][lane][5] = C * y * z - s * x;
        sR[w][lane][6] = C * x * z - s * y; sR[w][lane][7] = C * y * z + s * x; sR[w][lane][8] = c + C * z * z;
    }
    __syncwarp();

    for (int t = lane; t < 207; t += 32) {
        int jj = 1 + t / 9, e = t - (t / 9) * 9;
        d_LextT[t * NBODY + n] = sR[w][jj][e] - ((e == 0 || e == 4 || e == 8) ? 1.0f : 0.0f);
    }
    for (int t = lane; t < 17; t += 32) {
        int k = 207 + t;
        d_LextT[k * NBODY + n] = (t < 10) ? sBeta[w][t] : ((k == 217) ? 1.0f : 0.0f);
    }

    for (int t = lane; t < 72; t += 32) {
        int jj = t / 3, c = t - jj * 3;
        float s = d_Jt[jj * 3 + c];
#pragma unroll
        for (int b = 0; b < 10; b++) s += d_JS[(jj * 3 + c) * 10 + b] * sBeta[w][b];
        sJ[w][jj][c] = s;
    }
    __syncwarp();

    if (lane < 12) {
        int r = lane >> 2, cc = lane & 3;
        sG[w][0][lane] = (cc < 3) ? sR[w][0][r * 3 + cc] : sJ[w][0][r];
    }
    __syncwarp();
    for (int i = 1; i < NJ; i++) {
        int p = c_par[i];
        float val = 0.f;
        if (lane < 12) {
            int r = lane >> 2, cc = lane & 3;
            float t0, t1, t2;
            if (cc < 3) { t0 = sR[w][i][cc]; t1 = sR[w][i][3 + cc]; t2 = sR[w][i][6 + cc]; }
            else { t0 = sJ[w][i][0] - sJ[w][p][0]; t1 = sJ[w][i][1] - sJ[w][p][1]; t2 = sJ[w][i][2] - sJ[w][p][2]; }
            val = sG[w][p][r * 4 + 0] * t0 + sG[w][p][r * 4 + 1] * t1 + sG[w][p][r * 4 + 2] * t2;
            if (cc == 3) val += sG[w][p][r * 4 + 3];
        }
        __syncwarp();
        if (lane < 12) sG[w][i][lane] = val;
        __syncwarp();
    }

    for (int t = lane; t < 72; t += 32) {
        int jj = t / 3, r = t - jj * 3;
        float rj = sG[w][jj][r * 4 + 0] * sJ[w][jj][0] + sG[w][jj][r * 4 + 1] * sJ[w][jj][1]
                 + sG[w][jj][r * 4 + 2] * sJ[w][jj][2];
        sG[w][jj][r * 4 + 3] -= rj;
    }
    __syncwarp();
    for (int t = lane; t < NJ * 12; t += 32) {
        float g = sG[w][t / 12][t - (t / 12) * 12];
        if (n & 1) d_Gm2[(n >> 1) * (NJ * 12) + t].y = g;
        else       d_Gm2[(n >> 1) * (NJ * 12) + t].x = g;
    }
}

// ---------------------------------------------------------------------------
// Main fused kernel. 128 thr = 16 tx x 8 ty. Tile 64 bodies x 32 verts.
// Phase 1: cp.async double-buffered GEMM (R4 inner loop, unchanged).
// Phase 2: LBS with cp.async double-buffered G chunks.
// ---------------------------------------------------------------------------
#define AS_OFF(buf, kk, c) ((buf) * 2048 + (kk) * 64 + (c))
#define BS_OFF(buf, kk, c) (4096 + (buf) * 3200 + (kk) * 100 + (c))
#define GS_STRIDE 74   /* float2 units: rows 16B-aligned (592B), ty rows bank-disjoint */
#define GBUF_F2 2368   /* 32 * 74 */
#define WS_OFF 9472    /* floats; after 2 G buffers (2*2368 float2 = 9472 floats) */

__global__ void __launch_bounds__(128, 4)
smpl_main_kernel(const float* __restrict__ weights, float* __restrict__ out)
{
    __shared__ __align__(16) float smemf[10496];   // 42 KB

    float2* Gs2 = (float2*)smemf;
    float* Ws = smemf + WS_OFF;

    int tid = threadIdx.x;
    int tx = tid & 15, ty = tid >> 4;
    int nBase = blockIdx.y * BN;
    int vBase = blockIdx.x * BV;
    int colBase = blockIdx.x * 96;
    int pBase = nBase >> 1;

    unsigned smem_base = (unsigned)__cvta_generic_to_shared(smemf);

    ull vp2[4][6];
#pragma unroll
    for (int p = 0; p < 4; p++)
#pragma unroll
        for (int j = 0; j < 6; j++) vp2[p][j] = 0ull;

    // ---- Phase 1 prologue: async-load tile 0 into buf 0 ----
    {
#pragma unroll
        for (int t = 0; t < 4; t++) {
            int idx = tid + t * 128;
            int kk = idx >> 4, c4 = idx & 15;
            cp_async16(smem_base + AS_OFF(0, kk, c4 * 4) * 4,
                       &d_LextT[kk * NBODY + nBase + c4 * 4]);
        }
#pragma unroll
        for (int t = 0; t < 6; t++) {
            int idx = tid + t * 128;
            int kk = idx / 24, c4 = idx - kk * 24;
            cp_async16(smem_base + BS_OFF(0, kk, c4 * 4) * 4,
                       &d_PextT[(size_t)kk * NCOLPAD + colBase + c4 * 4]);
        }
        cp_commit();
    }

    for (int tt = 0; tt < 7; tt++) {
        int cur = tt & 1;
        if (tt < 6) {
            int nb = cur ^ 1;
            int k1 = (tt + 1) * 32;
#pragma unroll
            for (int t = 0; t < 4; t++) {
                int idx = tid + t * 128;
                int kk = idx >> 4, c4 = idx & 15;
                cp_async16(smem_base + AS_OFF(nb, kk, c4 * 4) * 4,
                           &d_LextT[(k1 + kk) * NBODY + nBase + c4 * 4]);
            }
#pragma unroll
            for (int t = 0; t < 6; t++) {
                int idx = tid + t * 128;
                int kk = idx / 24, c4 = idx - kk * 24;
                cp_async16(smem_base + BS_OFF(nb, kk, c4 * 4) * 4,
                           &d_PextT[(size_t)(k1 + kk) * NCOLPAD + colBase + c4 * 4]);
            }
            cp_commit();
            cp_wait<1>();
        } else {
            cp_wait<0>();
        }
        __syncthreads();

#pragma unroll
        for (int kk = 0; kk < 32; kk++) {
            ulonglong2 A0 = *(const ulonglong2*)&smemf[AS_OFF(cur, kk, ty * 8)];
            ulonglong2 A1 = *(const ulonglong2*)&smemf[AS_OFF(cur, kk, ty * 8 + 4)];
            float2 b01 = *(const float2*)&smemf[BS_OFF(cur, kk, tx * 6)];
            float2 b23 = *(const float2*)&smemf[BS_OFF(cur, kk, tx * 6 + 2)];
            float2 b45 = *(const float2*)&smemf[BS_OFF(cur, kk, tx * 6 + 4)];
            ull bd[6];
            bd[0] = dup2(b01.x); bd[1] = dup2(b01.y);
            bd[2] = dup2(b23.x); bd[3] = dup2(b23.y);
            bd[4] = dup2(b45.x); bd[5] = dup2(b45.y);
#pragma unroll
            for (int j = 0; j < 6; j++) {
                vp2[0][j] = ffma2(A0.x, bd[j], vp2[0][j]);
                vp2[1][j] = ffma2(A0.y, bd[j], vp2[1][j]);
                vp2[2][j] = ffma2(A1.x, bd[j], vp2[2][j]);
                vp2[3][j] = ffma2(A1.y, bd[j], vp2[3][j]);
            }
        }
        __syncthreads();
    }
    // all warps past final sync: phase-1 smem free for reuse

    // ---- Phase 2 prologue: prefetch G chunk 0, load Ws ----
    {
#pragma unroll
        for (int i = 0; i < 9; i++) {
            int t = tid + i * 128;
            int pl = t / 36, seg = t - pl * 36;
            cp_async16(smem_base + (pl * GS_STRIDE + seg * 2) * 8,
                       &d_Gm2[(pBase + pl) * (NJ * 12) + seg * 2]);
        }
        cp_commit();
    }
    for (int t = tid; t < BV * 24; t += 128) {
        int vl = t / 24, j2 = t - vl * 24;
        int v = vBase + vl;
        Ws[vl * 25 + j2] = (v < NVERT) ? weights[v * 24 + j2] : 0.f;
    }

    ull o2[4][6];
#pragma unroll
    for (int p = 0; p < 4; p++)
#pragma unroll
        for (int j = 0; j < 6; j++) o2[p][j] = 0ull;

    for (int jc = 0; jc < 4; jc++) {
        int cur = jc & 1;
        if (jc < 3) {
            int nb = cur ^ 1;
#pragma unroll
            for (int i = 0; i < 9; i++) {
                int t = tid + i * 128;
                int pl = t / 36, seg = t - pl * 36;
                cp_async16(smem_base + (nb * GBUF_F2 + pl * GS_STRIDE + seg * 2) * 8,
                           &d_Gm2[(pBase + pl) * (NJ * 12) + (jc + 1) * 72 + seg * 2]);
            }
            cp_commit();
            cp_wait<1>();
        } else {
            cp_wait<0>();
        }
        __syncthreads();
#pragma unroll
        for (int jj = 0; jj < 6; jj++) {
            ull w0 = dup2(Ws[(tx * 2) * 25 + jc * 6 + jj]);
            ull w1 = dup2(Ws[(tx * 2 + 1) * 25 + jc * 6 + jj]);
#pragma unroll
            for (int q = 0; q < 4; q++) {
                const ull* g = (const ull*)&Gs2[cur * GBUF_F2 + (ty * 4 + q) * GS_STRIDE + jj * 12];
#pragma unroll
                for (int c = 0; c < 3; c++) {
                    ull g0 = g[c * 4 + 0], g1 = g[c * 4 + 1];
                    ull g2 = g[c * 4 + 2], g3 = g[c * 4 + 3];
                    ull t0 = ffma2(g0, vp2[q][0], ffma2(g1, vp2[q][1], ffma2(g2, vp2[q][2], g3)));
                    o2[q][c] = ffma2(w0, t0, o2[q][c]);
                    ull t1 = ffma2(g0, vp2[q][3], ffma2(g1, vp2[q][4], ffma2(g2, vp2[q][5], g3)));
                    o2[q][3 + c] = ffma2(w1, t1, o2[q][3 + c]);
                }
            }
        }
        __syncthreads();
    }

    // ---- Store ----
#pragma unroll
    for (int q = 0; q < 4; q++) {
        int n0 = nBase + ty * 8 + 2 * q;
#pragma unroll
        for (int vv = 0; vv < 2; vv++) {
            int v = vBase + tx * 2 + vv;
            if (v < NVERT) {
                size_t b0 = ((size_t)n0 * NVERT + v) * 3;
                size_t b1 = ((size_t)(n0 + 1) * NVERT + v) * 3;
#pragma unroll
                for (int c = 0; c < 3; c++) {
                    float2 pr = unpack2(o2[q][vv * 3 + c]);
                    out[b0 + c] = pr.x;
                    out[b1 + c] = pr.y;
                }
            }
        }
    }
}

// ---------------------------------------------------------------------------
extern "C" void kernel_launch(void* const* d_in, const int* in_sizes, int n_in,
                              void* d_out, int out_size)
{
    const float* beta        = (const float*)d_in[0];
    const float* pose        = (const float*)d_in[1];
    const float* v_template  = (const float*)d_in[2];
    const float* shapedirs   = (const float*)d_in[3];
    const float* posedirs    = (const float*)d_in[4];
    const float* J_regressor = (const float*)d_in[5];
    const float* weights     = (const float*)d_in[6];
    float* out = (float*)d_out;

    prep_kernel<<<4608, dim3(32, 8)>>>(posedirs, shapedirs, v_template, J_regressor);
    body_kernel<<<NBODY / 8, 256>>>(beta, pose);
    smpl_main_kernel<<<dim3(NTILE, NBODY / BN), 128>>>(weights, out);
}

// round 8
// speedup vs baseline: 1.4068x; 1.1150x over previous
#include <cuda_runtime.h>
#include <math.h>

#define NBODY 512
#define NVERT 6890
#define NJ 24
#define NCOL (NVERT*3)
#define KP 224               /* 207 pose + 10 beta + 1 template + 6 zero pad */
#define NTILE 216
#define NCOLPAD (NTILE*96)   /* 20736, col = v*3+c */
#define BN 64
#define BV 32

typedef unsigned long long ull;

// Scratch (device globals — no allocation anywhere)
__device__ float d_PextT[(size_t)KP * NCOLPAD]; // [k][col], col = v*3+c
__device__ float d_LextT[KP * NBODY];           // [k][body]
__device__ float2 d_Gm2[(NBODY/2) * NJ * 12];   // body-pair interleaved
__device__ float d_JS[NJ * 3 * 10];
__device__ float d_Jt[NJ * 3];

__constant__ int c_par[NJ] = {0,0,0,0,1,2,3,4,5,6,7,8,9,9,9,12,13,14,16,17,18,19,20,21};

// ---- packed f32x2 helpers -------------------------------------------------
__device__ __forceinline__ ull ffma2(ull a, ull b, ull c) {
    ull d;
    asm("fma.rn.f32x2 %0, %1, %2, %3;" : "=l"(d) : "l"(a), "l"(b), "l"(c));
    return d;
}
__device__ __forceinline__ ull dup2(float x) {
    ull d; unsigned u = __float_as_uint(x);
    asm("mov.b64 %0, {%1, %1};" : "=l"(d) : "r"(u));
    return d;
}
__device__ __forceinline__ float2 unpack2(ull p) {
    float2 r;
    asm("mov.b64 {%0, %1}, %2;" : "=f"(r.x), "=f"(r.y) : "l"(p));
    return r;
}
// ---- cp.async helpers ------------------------------------------------------
__device__ __forceinline__ void cp_async16(unsigned s, const void* g) {
    asm volatile("cp.async.cg.shared.global [%0], [%1], 16;\n" :: "r"(s), "l"(g));
}
__device__ __forceinline__ void cp_commit() {
    asm volatile("cp.async.commit_group;\n");
}
template<int N> __device__ __forceinline__ void cp_wait() {
    asm volatile("cp.async.wait_group %0;\n" :: "n"(N));
}

// ---------------------------------------------------------------------------
// Fused prep, grid 720:
//  blocks [0,648): transpose one 32-col strip across full K=224 into PextT.
//    28 front-batched coalesced loads/thread -> smem [32][229] -> 28 coalesced
//    stores/thread. 229 % 32 = 5 (odd) -> conflict-free transposed smem reads.
//  blocks [648,720): fold J_regressor into shape space (72 = joint*coord).
// blockDim = (32,8).
// ---------------------------------------------------------------------------
__global__ void __launch_bounds__(256)
prep_kernel(const float* __restrict__ posedirs,
            const float* __restrict__ shapedirs,
            const float* __restrict__ v_template,
            const float* __restrict__ Jreg)
{
    int bid = blockIdx.x;
    int tx = threadIdx.x, ty = threadIdx.y;
    if (bid < 648) {
        __shared__ float tile[32][229];
        int rbase = bid * 32;
#pragma unroll
        for (int kk0 = 0; kk0 < KP; kk0 += 32) {
            int k = kk0 + tx;
#pragma unroll
            for (int i = 0; i < 4; i++) {
                int r = ty * 4 + i;
                int row = rbase + r;
                float v = 0.f;
                if (row < NCOL) {
                    if (k < 207)       v = posedirs[row * 207 + k];
                    else if (k < 217)  v = shapedirs[row * 10 + (k - 207)];
                    else if (k == 217) v = v_template[row];
                }
                tile[r][k] = v;
            }
        }
        __syncthreads();
#pragma unroll
        for (int q = 0; q < 28; q++) {
            int k = q * 8 + ty;
            d_PextT[(size_t)k * NCOLPAD + rbase + tx] = tile[tx][k];
        }
    } else {
        int jc = bid - 648;
        int j = jc / 3, c = jc - j * 3;
        int tid = ty * 32 + tx;
        float acc[11];
#pragma unroll
        for (int q = 0; q < 11; q++) acc[q] = 0.f;
        for (int v = tid; v < NVERT; v += 256) {
            float jr = Jreg[j * NVERT + v];
            acc[0] += jr * v_template[v * 3 + c];
#pragma unroll
            for (int b = 0; b < 10; b++)
                acc[1 + b] += jr * shapedirs[(v * 3 + c) * 10 + b];
        }
        __shared__ float red[8][11];
        int lane = tid & 31, wid = tid >> 5;
#pragma unroll
        for (int q = 0; q < 11; q++) {
            float s = acc[q];
            for (int o = 16; o; o >>= 1) s += __shfl_down_sync(0xffffffffu, s, o);
            if (lane == 0) red[wid][q] = s;
        }
        __syncthreads();
        if (tid < 11) {
            int q = tid;
            float s = 0.f;
            for (int w = 0; w < 8; w++) s += red[w][q];
            if (q == 0) d_Jt[j * 3 + c] = s;
            else        d_JS[(j * 3 + c) * 10 + (q - 1)] = s;
        }
    }
}

// ---------------------------------------------------------------------------
// Per-body prep: Rodrigues, LextT, joints, chain, G'. 8 warps/block, 1 warp/body.
// ---------------------------------------------------------------------------
__global__ void __launch_bounds__(256)
body_kernel(const float* __restrict__ beta, const float* __restrict__ pose)
{
    int w = threadIdx.x >> 5;
    int lane = threadIdx.x & 31;
    int n = blockIdx.x * 8 + w;

    __shared__ float sR[8][NJ][9];
    __shared__ float sJ[8][NJ][3];
    __shared__ float sG[8][NJ][12];
    __shared__ float sBeta[8][10];

    if (lane < 10) sBeta[w][lane] = beta[n * 10 + lane];
    if (lane < NJ) {
        float x = pose[n * 72 + lane * 3 + 0];
        float y = pose[n * 72 + lane * 3 + 1];
        float z = pose[n * 72 + lane * 3 + 2];
        float th = sqrtf(x * x + y * y + z * z) + 1e-8f;
        float inv = 1.0f / th;
        x *= inv; y *= inv; z *= inv;
        float s, c;
        sincosf(th, &s, &c);
        float C = 1.0f - c;
        sR[w][lane][0] = c + C * x * x;     sR[w][lane][1] = C * x * y - s * z; sR[w][lane][2] = C * x * z + s * y;
        sR[w][lane][3] = C * x * y + s * z; sR[w][lane][4] = c + C * y * y;     sR[w][lane][5] = C * y * z - s * x;
        sR[w][lane][6] = C * x * z - s * y; sR[w][lane][7] = C * y * z + s * x; sR[w][lane][8] = c + C * z * z;
    }
    __syncwarp();

    for (int t = lane; t < 207; t += 32) {
        int jj = 1 + t / 9, e = t - (t / 9) * 9;
        d_LextT[t * NBODY + n] = sR[w][jj][e] - ((e == 0 || e == 4 || e == 8) ? 1.0f : 0.0f);
    }
    for (int t = lane; t < 17; t += 32) {
        int k = 207 + t;
        d_LextT[k * NBODY + n] = (t < 10) ? sBeta[w][t] : ((k == 217) ? 1.0f : 0.0f);
    }

    for (int t = lane; t < 72; t += 32) {
        int jj = t / 3, c = t - jj * 3;
        float s = d_Jt[jj * 3 + c];
#pragma unroll
        for (int b = 0; b < 10; b++) s += d_JS[(jj * 3 + c) * 10 + b] * sBeta[w][b];
        sJ[w][jj][c] = s;
    }
    __syncwarp();

    if (lane < 12) {
        int r = lane >> 2, cc = lane & 3;
        sG[w][0][lane] = (cc < 3) ? sR[w][0][r * 3 + cc] : sJ[w][0][r];
    }
    __syncwarp();
    for (int i = 1; i < NJ; i++) {
        int p = c_par[i];
        float val = 0.f;
        if (lane < 12) {
            int r = lane >> 2, cc = lane & 3;
            float t0, t1, t2;
            if (cc < 3) { t0 = sR[w][i][cc]; t1 = sR[w][i][3 + cc]; t2 = sR[w][i][6 + cc]; }
            else { t0 = sJ[w][i][0] - sJ[w][p][0]; t1 = sJ[w][i][1] - sJ[w][p][1]; t2 = sJ[w][i][2] - sJ[w][p][2]; }
            val = sG[w][p][r * 4 + 0] * t0 + sG[w][p][r * 4 + 1] * t1 + sG[w][p][r * 4 + 2] * t2;
            if (cc == 3) val += sG[w][p][r * 4 + 3];
        }
        __syncwarp();
        if (lane < 12) sG[w][i][lane] = val;
        __syncwarp();
    }

    for (int t = lane; t < 72; t += 32) {
        int jj = t / 3, r = t - jj * 3;
        float rj = sG[w][jj][r * 4 + 0] * sJ[w][jj][0] + sG[w][jj][r * 4 + 1] * sJ[w][jj][1]
                 + sG[w][jj][r * 4 + 2] * sJ[w][jj][2];
        sG[w][jj][r * 4 + 3] -= rj;
    }
    __syncwarp();
    for (int t = lane; t < NJ * 12; t += 32) {
        float g = sG[w][t / 12][t - (t / 12) * 12];
        if (n & 1) d_Gm2[(n >> 1) * (NJ * 12) + t].y = g;
        else       d_Gm2[(n >> 1) * (NJ * 12) + t].x = g;
    }
}

// ---------------------------------------------------------------------------
// Main fused kernel. 128 thr = 16 tx x 8 ty. Tile 64 bodies x 32 verts.
// Phase 1: cp.async double-buffered GEMM. Phase 2: cp.async double-buffered LBS.
// (Unchanged from R6 — passing at rel_err 2e-7.)
// ---------------------------------------------------------------------------
#define AS_OFF(buf, kk, c) ((buf) * 2048 + (kk) * 64 + (c))
#define BS_OFF(buf, kk, c) (4096 + (buf) * 3200 + (kk) * 100 + (c))
#define GS_STRIDE 74
#define GBUF_F2 2368
#define WS_OFF 9472

__global__ void __launch_bounds__(128, 4)
smpl_main_kernel(const float* __restrict__ weights, float* __restrict__ out)
{
    __shared__ __align__(16) float smemf[10496];   // 42 KB

    float2* Gs2 = (float2*)smemf;
    float* Ws = smemf + WS_OFF;

    int tid = threadIdx.x;
    int tx = tid & 15, ty = tid >> 4;
    int nBase = blockIdx.y * BN;
    int vBase = blockIdx.x * BV;
    int colBase = blockIdx.x * 96;
    int pBase = nBase >> 1;

    unsigned smem_base = (unsigned)__cvta_generic_to_shared(smemf);

    ull vp2[4][6];
#pragma unroll
    for (int p = 0; p < 4; p++)
#pragma unroll
        for (int j = 0; j < 6; j++) vp2[p][j] = 0ull;

    {
#pragma unroll
        for (int t = 0; t < 4; t++) {
            int idx = tid + t * 128;
            int kk = idx >> 4, c4 = idx & 15;
            cp_async16(smem_base + AS_OFF(0, kk, c4 * 4) * 4,
                       &d_LextT[kk * NBODY + nBase + c4 * 4]);
        }
#pragma unroll
        for (int t = 0; t < 6; t++) {
            int idx = tid + t * 128;
            int kk = idx / 24, c4 = idx - kk * 24;
            cp_async16(smem_base + BS_OFF(0, kk, c4 * 4) * 4,
                       &d_PextT[(size_t)kk * NCOLPAD + colBase + c4 * 4]);
        }
        cp_commit();
    }

    for (int tt = 0; tt < 7; tt++) {
        int cur = tt & 1;
        if (tt < 6) {
            int nb = cur ^ 1;
            int k1 = (tt + 1) * 32;
#pragma unroll
            for (int t = 0; t < 4; t++) {
                int idx = tid + t * 128;
                int kk = idx >> 4, c4 = idx & 15;
                cp_async16(smem_base + AS_OFF(nb, kk, c4 * 4) * 4,
                           &d_LextT[(k1 + kk) * NBODY + nBase + c4 * 4]);
            }
#pragma unroll
            for (int t = 0; t < 6; t++) {
                int idx = tid + t * 128;
                int kk = idx / 24, c4 = idx - kk * 24;
                cp_async16(smem_base + BS_OFF(nb, kk, c4 * 4) * 4,
                           &d_PextT[(size_t)(k1 + kk) * NCOLPAD + colBase + c4 * 4]);
            }
            cp_commit();
            cp_wait<1>();
        } else {
            cp_wait<0>();
        }
        __syncthreads();

#pragma unroll
        for (int kk = 0; kk < 32; kk++) {
            ulonglong2 A0 = *(const ulonglong2*)&smemf[AS_OFF(cur, kk, ty * 8)];
            ulonglong2 A1 = *(const ulonglong2*)&smemf[AS_OFF(cur, kk, ty * 8 + 4)];
            float2 b01 = *(const float2*)&smemf[BS_OFF(cur, kk, tx * 6)];
            float2 b23 = *(const float2*)&smemf[BS_OFF(cur, kk, tx * 6 + 2)];
            float2 b45 = *(const float2*)&smemf[BS_OFF(cur, kk, tx * 6 + 4)];
            ull bd[6];
            bd[0] = dup2(b01.x); bd[1] = dup2(b01.y);
            bd[2] = dup2(b23.x); bd[3] = dup2(b23.y);
            bd[4] = dup2(b45.x); bd[5] = dup2(b45.y);
#pragma unroll
            for (int j = 0; j < 6; j++) {
                vp2[0][j] = ffma2(A0.x, bd[j], vp2[0][j]);
                vp2[1][j] = ffma2(A0.y, bd[j], vp2[1][j]);
                vp2[2][j] = ffma2(A1.x, bd[j], vp2[2][j]);
                vp2[3][j] = ffma2(A1.y, bd[j], vp2[3][j]);
            }
        }
        __syncthreads();
    }

    // ---- Phase 2 prologue: prefetch G chunk 0, load Ws ----
    {
#pragma unroll
        for (int i = 0; i < 9; i++) {
            int t = tid + i * 128;
            int pl = t / 36, seg = t - pl * 36;
            cp_async16(smem_base + (pl * GS_STRIDE + seg * 2) * 8,
                       &d_Gm2[(pBase + pl) * (NJ * 12) + seg * 2]);
        }
        cp_commit();
    }
    for (int t = tid; t < BV * 24; t += 128) {
        int vl = t / 24, j2 = t - vl * 24;
        int v = vBase + vl;
        Ws[vl * 25 + j2] = (v < NVERT) ? weights[v * 24 + j2] : 0.f;
    }

    ull o2[4][6];
#pragma unroll
    for (int p = 0; p < 4; p++)
#pragma unroll
        for (int j = 0; j < 6; j++) o2[p][j] = 0ull;

    for (int jc = 0; jc < 4; jc++) {
        int cur = jc & 1;
        if (jc < 3) {
            int nb = cur ^ 1;
#pragma unroll
            for (int i = 0; i < 9; i++) {
                int t = tid + i * 128;
                int pl = t / 36, seg = t - pl * 36;
                cp_async16(smem_base + (nb * GBUF_F2 + pl * GS_STRIDE + seg * 2) * 8,
                           &d_Gm2[(pBase + pl) * (NJ * 12) + (jc + 1) * 72 + seg * 2]);
            }
            cp_commit();
            cp_wait<1>();
        } else {
            cp_wait<0>();
        }
        __syncthreads();
#pragma unroll
        for (int jj = 0; jj < 6; jj++) {
            ull w0 = dup2(Ws[(tx * 2) * 25 + jc * 6 + jj]);
            ull w1 = dup2(Ws[(tx * 2 + 1) * 25 + jc * 6 + jj]);
#pragma unroll
            for (int q = 0; q < 4; q++) {
                const ull* g = (const ull*)&Gs2[cur * GBUF_F2 + (ty * 4 + q) * GS_STRIDE + jj * 12];
#pragma unroll
                for (int c = 0; c < 3; c++) {
                    ull g0 = g[c * 4 + 0], g1 = g[c * 4 + 1];
                    ull g2 = g[c * 4 + 2], g3 = g[c * 4 + 3];
                    ull t0 = ffma2(g0, vp2[q][0], ffma2(g1, vp2[q][1], ffma2(g2, vp2[q][2], g3)));
                    o2[q][c] = ffma2(w0, t0, o2[q][c]);
                    ull t1 = ffma2(g0, vp2[q][3], ffma2(g1, vp2[q][4], ffma2(g2, vp2[q][5], g3)));
                    o2[q][3 + c] = ffma2(w1, t1, o2[q][3 + c]);
                }
            }
        }
        __syncthreads();
    }

    // ---- Store ----
#pragma unroll
    for (int q = 0; q < 4; q++) {
        int n0 = nBase + ty * 8 + 2 * q;
#pragma unroll
        for (int vv = 0; vv < 2; vv++) {
            int v = vBase + tx * 2 + vv;
            if (v < NVERT) {
                size_t b0 = ((size_t)n0 * NVERT + v) * 3;
                size_t b1 = ((size_t)(n0 + 1) * NVERT + v) * 3;
#pragma unroll
                for (int c = 0; c < 3; c++) {
                    float2 pr = unpack2(o2[q][vv * 3 + c]);
                    out[b0 + c] = pr.x;
                    out[b1 + c] = pr.y;
                }
            }
        }
    }
}

// ---------------------------------------------------------------------------
extern "C" void kernel_launch(void* const* d_in, const int* in_sizes, int n_in,
                              void* d_out, int out_size)
{
    const float* beta        = (const float*)d_in[0];
    const float* pose        = (const float*)d_in[1];
    const float* v_template  = (const float*)d_in[2];
    const float* shapedirs   = (const float*)d_in[3];
    const float* posedirs    = (const float*)d_in[4];
    const float* J_regressor = (const float*)d_in[5];
    const float* weights     = (const float*)d_in[6];
    float* out = (float*)d_out;

    prep_kernel<<<720, dim3(32, 8)>>>(posedirs, shapedirs, v_template, J_regressor);
    body_kernel<<<NBODY / 8, 256>>>(beta, pose);
    smpl_main_kernel<<<dim3(NTILE, NBODY / BN), 128>>>(weights, out);
}

// round 9
// speedup vs baseline: 1.4191x; 1.0087x over previous
#include <cuda_runtime.h>
#include <math.h>

#define NBODY 512
#define NVERT 6890
#define NJ 24
#define NCOL (NVERT*3)
#define KP 224               /* 207 pose + 10 beta + 1 template + 6 zero pad */
#define NTILE 216
#define NCOLPAD (NTILE*96)   /* 20736, col = v*3+c */
#define BN 64
#define BV 32

typedef unsigned long long ull;

// Scratch (device globals — no allocation anywhere)
__device__ float d_PextT[(size_t)KP * NCOLPAD]; // [k][col], col = v*3+c
__device__ float d_LextT[KP * NBODY];           // [k][body]
__device__ float2 d_Gm2[(NBODY/2) * NJ * 12];   // body-pair interleaved
__device__ float d_JS[NJ * 3 * 10];
__device__ float d_Jt[NJ * 3];

__constant__ int c_par[NJ] = {0,0,0,0,1,2,3,4,5,6,7,8,9,9,9,12,13,14,16,17,18,19,20,21};

// ---- packed f32x2 helpers -------------------------------------------------
__device__ __forceinline__ ull ffma2(ull a, ull b, ull c) {
    ull d;
    asm("fma.rn.f32x2 %0, %1, %2, %3;" : "=l"(d) : "l"(a), "l"(b), "l"(c));
    return d;
}
__device__ __forceinline__ ull dup2(float x) {
    ull d; unsigned u = __float_as_uint(x);
    asm("mov.b64 %0, {%1, %1};" : "=l"(d) : "r"(u));
    return d;
}
__device__ __forceinline__ float2 unpack2(ull p) {
    float2 r;
    asm("mov.b64 {%0, %1}, %2;" : "=f"(r.x), "=f"(r.y) : "l"(p));
    return r;
}
// ---- cp.async helpers ------------------------------------------------------
__device__ __forceinline__ void cp_async16(unsigned s, const void* g) {
    asm volatile("cp.async.cg.shared.global [%0], [%1], 16;\n" :: "r"(s), "l"(g));
}
__device__ __forceinline__ void cp_commit() {
    asm volatile("cp.async.commit_group;\n");
}
template<int N> __device__ __forceinline__ void cp_wait() {
    asm volatile("cp.async.wait_group %0;\n" :: "n"(N));
}

// ---------------------------------------------------------------------------
// Fused prep, grid 720:
//  blocks [0,648): transpose one 32-col strip across full K=224 into PextT.
//    All 28 loads register-batched (MLP ~28) -> STS burst -> coalesced stores.
//  blocks [648,720): fold J_regressor into shape space (72 = joint*coord).
// blockDim = (32,8).
// ---------------------------------------------------------------------------
__global__ void __launch_bounds__(256)
prep_kernel(const float* __restrict__ posedirs,
            const float* __restrict__ shapedirs,
            const float* __restrict__ v_template,
            const float* __restrict__ Jreg)
{
    int bid = blockIdx.x;
    int tx = threadIdx.x, ty = threadIdx.y;
    if (bid < 648) {
        __shared__ float tile[32][229];
        int rbase = bid * 32;
        float r[28];
        // 1) front-batched predicated loads: 28 independent LDGs per thread
#pragma unroll
        for (int q = 0; q < 28; q++) {
            int kk0 = (q >> 2) * 32;
            int i = q & 3;
            int row = rbase + ty * 4 + i;
            int k = kk0 + tx;
            float v = 0.f;
            if (row < NCOL) {
                if (k < 207)       v = posedirs[row * 207 + k];
                else if (k < 217)  v = shapedirs[row * 10 + (k - 207)];
                else if (k == 217) v = v_template[row];
            }
            r[q] = v;
        }
        // 2) STS burst
#pragma unroll
        for (int q = 0; q < 28; q++) {
            int kk0 = (q >> 2) * 32;
            int i = q & 3;
            tile[ty * 4 + i][kk0 + tx] = r[q];
        }
        __syncthreads();
        // 3) transposed smem reads (stride 229 -> conflict-free), coalesced stores
#pragma unroll
        for (int q = 0; q < 28; q++) {
            int k = q * 8 + ty;
            d_PextT[(size_t)k * NCOLPAD + rbase + tx] = tile[tx][k];
        }
    } else {
        int jc = bid - 648;
        int j = jc / 3, c = jc - j * 3;
        int tid = ty * 32 + tx;
        float acc[11];
#pragma unroll
        for (int q = 0; q < 11; q++) acc[q] = 0.f;
        for (int v = tid; v < NVERT; v += 256) {
            float jr = Jreg[j * NVERT + v];
            acc[0] += jr * v_template[v * 3 + c];
#pragma unroll
            for (int b = 0; b < 10; b++)
                acc[1 + b] += jr * shapedirs[(v * 3 + c) * 10 + b];
        }
        __shared__ float red[8][11];
        int lane = tid & 31, wid = tid >> 5;
#pragma unroll
        for (int q = 0; q < 11; q++) {
            float s = acc[q];
            for (int o = 16; o; o >>= 1) s += __shfl_down_sync(0xffffffffu, s, o);
            if (lane == 0) red[wid][q] = s;
        }
        __syncthreads();
        if (tid < 11) {
            int q = tid;
            float s = 0.f;
            for (int w = 0; w < 8; w++) s += red[w][q];
            if (q == 0) d_Jt[j * 3 + c] = s;
            else        d_JS[(j * 3 + c) * 10 + (q - 1)] = s;
        }
    }
}

// ---------------------------------------------------------------------------
// Per-body prep: Rodrigues, LextT, joints, chain, G'. 8 warps/block, 1 warp/body.
// ---------------------------------------------------------------------------
__global__ void __launch_bounds__(256)
body_kernel(const float* __restrict__ beta, const float* __restrict__ pose)
{
    int w = threadIdx.x >> 5;
    int lane = threadIdx.x & 31;
    int n = blockIdx.x * 8 + w;

    __shared__ float sR[8][NJ][9];
    __shared__ float sJ[8][NJ][3];
    __shared__ float sG[8][NJ][12];
    __shared__ float sBeta[8][10];

    if (lane < 10) sBeta[w][lane] = beta[n * 10 + lane];
    if (lane < NJ) {
        float x = pose[n * 72 + lane * 3 + 0];
        float y = pose[n * 72 + lane * 3 + 1];
        float z = pose[n * 72 + lane * 3 + 2];
        float th = sqrtf(x * x + y * y + z * z) + 1e-8f;
        float inv = 1.0f / th;
        x *= inv; y *= inv; z *= inv;
        float s, c;
        sincosf(th, &s, &c);
        float C = 1.0f - c;
        sR[w][lane][0] = c + C * x * x;     sR[w][lane][1] = C * x * y - s * z; sR[w][lane][2] = C * x * z + s * y;
        sR[w][lane][3] = C * x * y + s * z; sR[w][lane][4] = c + C * y * y;     sR[w][lane][5] = C * y * z - s * x;
        sR[w][lane][6] = C * x * z - s * y; sR[w][lane][7] = C * y * z + s * x; sR[w][lane][8] = c + C * z * z;
    }
    __syncwarp();

    for (int t = lane; t < 207; t += 32) {
        int jj = 1 + t / 9, e = t - (t / 9) * 9;
        d_LextT[t * NBODY + n] = sR[w][jj][e] - ((e == 0 || e == 4 || e == 8) ? 1.0f : 0.0f);
    }
    for (int t = lane; t < 17; t += 32) {
        int k = 207 + t;
        d_LextT[k * NBODY + n] = (t < 10) ? sBeta[w][t] : ((k == 217) ? 1.0f : 0.0f);
    }

    for (int t = lane; t < 72; t += 32) {
        int jj = t / 3, c = t - jj * 3;
        float s = d_Jt[jj * 3 + c];
#pragma unroll
        for (int b = 0; b < 10; b++) s += d_JS[(jj * 3 + c) * 10 + b] * sBeta[w][b];
        sJ[w][jj][c] = s;
    }
    __syncwarp();

    if (lane < 12) {
        int r = lane >> 2, cc = lane & 3;
        sG[w][0][lane] = (cc < 3) ? sR[w][0][r * 3 + cc] : sJ[w][0][r];
    }
    __syncwarp();
    for (int i = 1; i < NJ; i++) {
        int p = c_par[i];
        float val = 0.f;
        if (lane < 12) {
            int r = lane >> 2, cc = lane & 3;
            float t0, t1, t2;
            if (cc < 3) { t0 = sR[w][i][cc]; t1 = sR[w][i][3 + cc]; t2 = sR[w][i][6 + cc]; }
            else { t0 = sJ[w][i][0] - sJ[w][p][0]; t1 = sJ[w][i][1] - sJ[w][p][1]; t2 = sJ[w][i][2] - sJ[w][p][2]; }
            val = sG[w][p][r * 4 + 0] * t0 + sG[w][p][r * 4 + 1] * t1 + sG[w][p][r * 4 + 2] * t2;
            if (cc == 3) val += sG[w][p][r * 4 + 3];
        }
        __syncwarp();
        if (lane < 12) sG[w][i][lane] = val;
        __syncwarp();
    }

    for (int t = lane; t < 72; t += 32) {
        int jj = t / 3, r = t - jj * 3;
        float rj = sG[w][jj][r * 4 + 0] * sJ[w][jj][0] + sG[w][jj][r * 4 + 1] * sJ[w][jj][1]
                 + sG[w][jj][r * 4 + 2] * sJ[w][jj][2];
        sG[w][jj][r * 4 + 3] -= rj;
    }
    __syncwarp();
    for (int t = lane; t < NJ * 12; t += 32) {
        float g = sG[w][t / 12][t - (t / 12) * 12];
        if (n & 1) d_Gm2[(n >> 1) * (NJ * 12) + t].y = g;
        else       d_Gm2[(n >> 1) * (NJ * 12) + t].x = g;
    }
}

// ---------------------------------------------------------------------------
// Main fused kernel. 128 thr = 16 tx x 8 ty. Tile 64 bodies x 32 verts.
// Phase 1: cp.async double-buffered GEMM. Phase 2: cp.async double-buffered LBS.
// (Unchanged from R7 — passing at rel_err 2e-7.)
// ---------------------------------------------------------------------------
#define AS_OFF(buf, kk, c) ((buf) * 2048 + (kk) * 64 + (c))
#define BS_OFF(buf, kk, c) (4096 + (buf) * 3200 + (kk) * 100 + (c))
#define GS_STRIDE 74
#define GBUF_F2 2368
#define WS_OFF 9472

__global__ void __launch_bounds__(128, 4)
smpl_main_kernel(const float* __restrict__ weights, float* __restrict__ out)
{
    __shared__ __align__(16) float smemf[10496];   // 42 KB

    float2* Gs2 = (float2*)smemf;
    float* Ws = smemf + WS_OFF;

    int tid = threadIdx.x;
    int tx = tid & 15, ty = tid >> 4;
    int nBase = blockIdx.y * BN;
    int vBase = blockIdx.x * BV;
    int colBase = blockIdx.x * 96;
    int pBase = nBase >> 1;

    unsigned smem_base = (unsigned)__cvta_generic_to_shared(smemf);

    ull vp2[4][6];
#pragma unroll
    for (int p = 0; p < 4; p++)
#pragma unroll
        for (int j = 0; j < 6; j++) vp2[p][j] = 0ull;

    {
#pragma unroll
        for (int t = 0; t < 4; t++) {
            int idx = tid + t * 128;
            int kk = idx >> 4, c4 = idx & 15;
            cp_async16(smem_base + AS_OFF(0, kk, c4 * 4) * 4,
                       &d_LextT[kk * NBODY + nBase + c4 * 4]);
        }
#pragma unroll
        for (int t = 0; t < 6; t++) {
            int idx = tid + t * 128;
            int kk = idx / 24, c4 = idx - kk * 24;
            cp_async16(smem_base + BS_OFF(0, kk, c4 * 4) * 4,
                       &d_PextT[(size_t)kk * NCOLPAD + colBase + c4 * 4]);
        }
        cp_commit();
    }

    for (int tt = 0; tt < 7; tt++) {
        int cur = tt & 1;
        if (tt < 6) {
            int nb = cur ^ 1;
            int k1 = (tt + 1) * 32;
#pragma unroll
            for (int t = 0; t < 4; t++) {
                int idx = tid + t * 128;
                int kk = idx >> 4, c4 = idx & 15;
                cp_async16(smem_base + AS_OFF(nb, kk, c4 * 4) * 4,
                           &d_LextT[(k1 + kk) * NBODY + nBase + c4 * 4]);
            }
#pragma unroll
            for (int t = 0; t < 6; t++) {
                int idx = tid + t * 128;
                int kk = idx / 24, c4 = idx - kk * 24;
                cp_async16(smem_base + BS_OFF(nb, kk, c4 * 4) * 4,
                           &d_PextT[(size_t)(k1 + kk) * NCOLPAD + colBase + c4 * 4]);
            }
            cp_commit();
            cp_wait<1>();
        } else {
            cp_wait<0>();
        }
        __syncthreads();

#pragma unroll
        for (int kk = 0; kk < 32; kk++) {
            ulonglong2 A0 = *(const ulonglong2*)&smemf[AS_OFF(cur, kk, ty * 8)];
            ulonglong2 A1 = *(const ulonglong2*)&smemf[AS_OFF(cur, kk, ty * 8 + 4)];
            float2 b01 = *(const float2*)&smemf[BS_OFF(cur, kk, tx * 6)];
            float2 b23 = *(const float2*)&smemf[BS_OFF(cur, kk, tx * 6 + 2)];
            float2 b45 = *(const float2*)&smemf[BS_OFF(cur, kk, tx * 6 + 4)];
            ull bd[6];
            bd[0] = dup2(b01.x); bd[1] = dup2(b01.y);
            bd[2] = dup2(b23.x); bd[3] = dup2(b23.y);
            bd[4] = dup2(b45.x); bd[5] = dup2(b45.y);
#pragma unroll
            for (int j = 0; j < 6; j++) {
                vp2[0][j] = ffma2(A0.x, bd[j], vp2[0][j]);
                vp2[1][j] = ffma2(A0.y, bd[j], vp2[1][j]);
                vp2[2][j] = ffma2(A1.x, bd[j], vp2[2][j]);
                vp2[3][j] = ffma2(A1.y, bd[j], vp2[3][j]);
            }
        }
        __syncthreads();
    }

    // ---- Phase 2 prologue: prefetch G chunk 0, load Ws ----
    {
#pragma unroll
        for (int i = 0; i < 9; i++) {
            int t = tid + i * 128;
            int pl = t / 36, seg = t - pl * 36;
            cp_async16(smem_base + (pl * GS_STRIDE + seg * 2) * 8,
                       &d_Gm2[(pBase + pl) * (NJ * 12) + seg * 2]);
        }
        cp_commit();
    }
    for (int t = tid; t < BV * 24; t += 128) {
        int vl = t / 24, j2 = t - vl * 24;
        int v = vBase + vl;
        Ws[vl * 25 + j2] = (v < NVERT) ? weights[v * 24 + j2] : 0.f;
    }

    ull o2[4][6];
#pragma unroll
    for (int p = 0; p < 4; p++)
#pragma unroll
        for (int j = 0; j < 6; j++) o2[p][j] = 0ull;

    for (int jc = 0; jc < 4; jc++) {
        int cur = jc & 1;
        if (jc < 3) {
            int nb = cur ^ 1;
#pragma unroll
            for (int i = 0; i < 9; i++) {
                int t = tid + i * 128;
                int pl = t / 36, seg = t - pl * 36;
                cp_async16(smem_base + (nb * GBUF_F2 + pl * GS_STRIDE + seg * 2) * 8,
                           &d_Gm2[(pBase + pl) * (NJ * 12) + (jc + 1) * 72 + seg * 2]);
            }
            cp_commit();
            cp_wait<1>();
        } else {
            cp_wait<0>();
        }
        __syncthreads();
#pragma unroll
        for (int jj = 0; jj < 6; jj++) {
            ull w0 = dup2(Ws[(tx * 2) * 25 + jc * 6 + jj]);
            ull w1 = dup2(Ws[(tx * 2 + 1) * 25 + jc * 6 + jj]);
#pragma unroll
            for (int q = 0; q < 4; q++) {
                const ull* g = (const ull*)&Gs2[cur * GBUF_F2 + (ty * 4 + q) * GS_STRIDE + jj * 12];
#pragma unroll
                for (int c = 0; c < 3; c++) {
                    ull g0 = g[c * 4 + 0], g1 = g[c * 4 + 1];
                    ull g2 = g[c * 4 + 2], g3 = g[c * 4 + 3];
                    ull t0 = ffma2(g0, vp2[q][0], ffma2(g1, vp2[q][1], ffma2(g2, vp2[q][2], g3)));
                    o2[q][c] = ffma2(w0, t0, o2[q][c]);
                    ull t1 = ffma2(g0, vp2[q][3], ffma2(g1, vp2[q][4], ffma2(g2, vp2[q][5], g3)));
                    o2[q][3 + c] = ffma2(w1, t1, o2[q][3 + c]);
                }
            }
        }
        __syncthreads();
    }

    // ---- Store ----
#pragma unroll
    for (int q = 0; q < 4; q++) {
        int n0 = nBase + ty * 8 + 2 * q;
#pragma unroll
        for (int vv = 0; vv < 2; vv++) {
            int v = vBase + tx * 2 + vv;
            if (v < NVERT) {
                size_t b0 = ((size_t)n0 * NVERT + v) * 3;
                size_t b1 = ((size_t)(n0 + 1) * NVERT + v) * 3;
#pragma unroll
                for (int c = 0; c < 3; c++) {
                    float2 pr = unpack2(o2[q][vv * 3 + c]);
                    out[b0 + c] = pr.x;
                    out[b1 + c] = pr.y;
                }
            }
        }
    }
}

// ---------------------------------------------------------------------------
extern "C" void kernel_launch(void* const* d_in, const int* in_sizes, int n_in,
                              void* d_out, int out_size)
{
    const float* beta        = (const float*)d_in[0];
    const float* pose        = (const float*)d_in[1];
    const float* v_template  = (const float*)d_in[2];
    const float* shapedirs   = (const float*)d_in[3];
    const float* posedirs    = (const float*)d_in[4];
    const float* J_regressor = (const float*)d_in[5];
    const float* weights     = (const float*)d_in[6];
    float* out = (float*)d_out;

    prep_kernel<<<720, dim3(32, 8)>>>(posedirs, shapedirs, v_template, J_regressor);
    body_kernel<<<NBODY / 8, 256>>>(beta, pose);
    smpl_main_kernel<<<dim3(NTILE, NBODY / BN), 128>>>(weights, out);
}